// round 7
// baseline (speedup 1.0000x reference)
#include <cuda_runtime.h>
#include <cuda_bf16.h>
#include <mma.h>
#include <cstdint>

using namespace nvcuda;

#define NN 8192
#define DD 64
#define MAXDEG 16
#define KK 8
#define LL 17            // MAXDEG + 1
#define DIN 128          // D * EXPAND
#define EPS 1e-5f

#define NODES_TILE 3
#define TROWS 64                          // padded rows per tile (51 valid)
#define TILES ((NN + NODES_TILE - 1)/NODES_TILE)   // 2731

// ---------------- device scratch ----------------
__device__ float g_hflat[NN*MAXDEG*DD];
__device__ float g_hinput[NN*LL*DD];
__device__ float g_y[NN*LL*DD];
__device__ float g_bnsum[DD];
__device__ float g_bnsq[DD];

__device__ __forceinline__ float sigm(float x) { return 1.f/(1.f+__expf(-x)); }

// smem byte offsets (k3)
#define SO_W1HI 0                  // [64 k][256 ch] bf16 = 32768
#define SO_W1LO 32768
#define SO_W2HI 65536              // [128 c][64 d] bf16 = 16384
#define SO_W2LO 81920
#define SO_HHI  98304              // [64 r][64 k] bf16 = 8192
#define SO_HLO  106496
#define SO_D2   98304              // [64 r][64 d] f32 = 16384 (alias H, used after fc1)
#define SO_D1   114688             // [64 r][256 ch] f32 = 65536
#define SO_GHI  180224             // [64 r][128 c] bf16 = 16384
#define SO_GLO  196608
#define SO_RR   212992             // 64 f32
#define SO_B2S  213248             // 64 f32
#define SO_BN   213504             // 512 f32
#define SMEM3   215552

// ---------------- K0: zero BN accumulators (graph replays!) ----------------
__global__ void kz() {
    int t = threadIdx.x;
    if (t < DD) { g_bnsum[t] = 0.f; g_bnsq[t] = 0.f; }
}

// ---------------- K1: message + mailbox rank-sort ----------------
__global__ void k1(const float* __restrict__ hs, const float* __restrict__ hs_e,
                   const float* __restrict__ degree, const float* __restrict__ noise) {
    int n = blockIdx.x*4 + (threadIdx.x >> 6);
    int d = threadIdx.x & 63;
    float h = hs[n*DD + d];
    float deg = __ldg(&degree[n]);
    float sc[KK];
#pragma unroll
    for (int k = 0; k < KK; k++) sc[k] = deg + __ldg(&noise[n*KK + k]);
#pragma unroll
    for (int k = 0; k < KK; k++) {
        float e = hs_e[(n*KK + k)*DD + d];
        float m = h * sigm(e);
        int r = 0;
#pragma unroll
        for (int j = 0; j < KK; j++)
            r += (sc[j] < sc[k]) || (sc[j] == sc[k] && j < k);
        g_hflat[n*(MAXDEG*DD) + r*DD + d] = m;
    }
#pragma unroll
    for (int j = KK; j < MAXDEG; j++)
        g_hflat[n*(MAXDEG*DD) + j*DD + d] = 0.f;
}

// ---------------- K2: (A+I) spmm gather ----------------
__global__ void k2(const float* __restrict__ hs, const int* __restrict__ src) {
    int n = blockIdx.x;
    int t = threadIdx.x;
    if (t < DD) g_hinput[n*(LL*DD) + t] = hs[n*DD + t];
    float4 a = ((const float4*)(g_hflat + n*(MAXDEG*DD)))[t];
#pragma unroll
    for (int k = 0; k < KK; k++) {
        int s = __ldg(&src[n*KK + k]);
        float4 v = ((const float4*)(g_hflat + s*(MAXDEG*DD)))[t];
        a.x += v.x; a.y += v.y; a.z += v.z; a.w += v.w;
    }
    ((float4*)(g_hinput + n*(LL*DD) + DD))[t] = a;
}

// ---------------- K3: wmma bf16 hi/lo GatedCNN ----------------
// persistent 148 CTAs x 256 threads; tile = 3 nodes = 51 rows (pad 64)
__global__ void __launch_bounds__(256, 1)
k3(const float* __restrict__ fc1w, const float* __restrict__ fc1b,
   const float* __restrict__ convw, const float* __restrict__ convb,
   const float* __restrict__ fc2w, const float* __restrict__ fc2b,
   const float* __restrict__ rmsw) {
    extern __shared__ char sm[];
    __nv_bfloat16* w1hi = (__nv_bfloat16*)(sm + SO_W1HI);
    __nv_bfloat16* w1lo = (__nv_bfloat16*)(sm + SO_W1LO);
    __nv_bfloat16* w2hi = (__nv_bfloat16*)(sm + SO_W2HI);
    __nv_bfloat16* w2lo = (__nv_bfloat16*)(sm + SO_W2LO);
    __nv_bfloat16* hhi  = (__nv_bfloat16*)(sm + SO_HHI);
    __nv_bfloat16* hlo  = (__nv_bfloat16*)(sm + SO_HLO);
    float* d2   = (float*)(sm + SO_D2);
    float* d1   = (float*)(sm + SO_D1);
    __nv_bfloat16* ghi  = (__nv_bfloat16*)(sm + SO_GHI);
    __nv_bfloat16* glo  = (__nv_bfloat16*)(sm + SO_GLO);
    float* rr   = (float*)(sm + SO_RR);
    float* b2s  = (float*)(sm + SO_B2S);
    float* bnp  = (float*)(sm + SO_BN);

    int t = threadIdx.x;
    int w = t >> 5;

    // ---- stage weights (hi/lo bf16, transposed) ----
    for (int i = t; i < 256*64; i += 256) {       // fc1w [ch][k] -> W1T[k][ch]
        int ch = i >> 6, k = i & 63;
        float v = fc1w[i];
        __nv_bfloat16 hi = __float2bfloat16(v);
        w1hi[k*256 + ch] = hi;
        w1lo[k*256 + ch] = __float2bfloat16(v - __bfloat162float(hi));
    }
    for (int i = t; i < 64*128; i += 256) {       // fc2w [d][c] -> W2T[c][d]
        int dch = i >> 7, c = i & 127;
        float v = fc2w[i];
        __nv_bfloat16 hi = __float2bfloat16(v);
        w2hi[c*64 + dch] = hi;
        w2lo[c*64 + dch] = __float2bfloat16(v - __bfloat162float(hi));
    }
    if (t < DD) b2s[t] = fc2b[t];

    // per-thread invariants
    int c = t & 127;                // conv channel
    int rh = t >> 7;                // conv row half
    float cw0 = __ldg(&convw[c*4+0]), cw1 = __ldg(&convw[c*4+1]);
    float cw2 = __ldg(&convw[c*4+2]), cw3 = __ldg(&convw[c*4+3]);
    float cb  = __ldg(&convb[c]);
    float b1x = __ldg(&fc1b[c]);
    float b1z = __ldg(&fc1b[DIN + c]);
    int dch = t & 63;               // y channel
    int r0y = (t >> 6) * 16;        // y row base
    float rw = __ldg(&rmsw[dch]);
    float bsum = 0.f, bsq = 0.f;

    // warp tile assignment
    int rt = w & 3;                 // row tile (16 rows)
    int ct0 = w >> 2;               // ch tile base (0/1)

    __syncthreads();

    for (int ti = blockIdx.x; ti < TILES; ti += 148) {
        int n0 = ti * NODES_TILE;
        int nvalid = min(NODES_TILE, NN - n0);
        int rvalid = nvalid * LL;
        const float* hsrc = g_hinput + (size_t)n0*(LL*DD);

        // ---- stage H tile (hi/lo bf16, row-major [64][64]) ----
        int vmax = rvalid * DD;
        for (int i = t; i < TROWS*DD; i += 256) {
            float v = (i < vmax) ? hsrc[i] : 0.f;
            __nv_bfloat16 hi = __float2bfloat16(v);
            hhi[i] = hi;
            hlo[i] = __float2bfloat16(v - __bfloat162float(hi));
        }
        __syncthreads();

        // ---- fc1: D1[64,256] = H[64,64] x W1T[64,256], 3-pass hi/lo ----
        {
            wmma::fragment<wmma::accumulator, 16, 16, 16, float> acc[8];
#pragma unroll
            for (int j = 0; j < 8; j++) wmma::fill_fragment(acc[j], 0.f);
            const __nv_bfloat16* As[3] = {hhi, hlo, hhi};
            const __nv_bfloat16* Bs[3] = {w1hi, w1hi, w1lo};
#pragma unroll
            for (int p = 0; p < 3; p++) {
#pragma unroll
                for (int ks = 0; ks < 4; ks++) {
                    wmma::fragment<wmma::matrix_a, 16, 16, 16, __nv_bfloat16, wmma::row_major> af;
                    wmma::load_matrix_sync(af, As[p] + rt*16*64 + ks*16, 64);
#pragma unroll
                    for (int j = 0; j < 8; j++) {
                        int ct = ct0 + 2*j;
                        wmma::fragment<wmma::matrix_b, 16, 16, 16, __nv_bfloat16, wmma::row_major> bf;
                        wmma::load_matrix_sync(bf, Bs[p] + ks*16*256 + ct*16, 256);
                        wmma::mma_sync(acc[j], af, bf, acc[j]);
                    }
                }
            }
#pragma unroll
            for (int j = 0; j < 8; j++)
                wmma::store_matrix_sync(d1 + rt*16*256 + (ct0 + 2*j)*16, acc[j], 256, wmma::mem_row_major);
        }
        __syncthreads();

        // ---- conv + gate -> G tiles (hi/lo bf16) ----
        for (int ri = 0; ri < 32; ri++) {
            int r = rh*32 + ri;
            if (r < rvalid) {
                int l = r % LL;
                float xc = cb + (d1[r*256 + c] + b1x)*cw3;
                if (l >= 1) xc += (d1[(r-1)*256 + c] + b1x)*cw2;
                if (l >= 2) xc += (d1[(r-2)*256 + c] + b1x)*cw1;
                if (l >= 3) xc += (d1[(r-3)*256 + c] + b1x)*cw0;
                float z = d1[r*256 + DIN + c] + b1z;
                float g = (xc*sigm(xc)) * (z*sigm(z));
                __nv_bfloat16 hi = __float2bfloat16(g);
                ghi[r*DIN + c] = hi;
                glo[r*DIN + c] = __float2bfloat16(g - __bfloat162float(hi));
            } else {
                ghi[r*DIN + c] = __float2bfloat16(0.f);
                glo[r*DIN + c] = __float2bfloat16(0.f);
            }
        }
        __syncthreads();

        // ---- fc2: D2[64,64] = G[64,128] x W2T[128,64], 3-pass ----
        {
            wmma::fragment<wmma::accumulator, 16, 16, 16, float> acc2[2];
#pragma unroll
            for (int j = 0; j < 2; j++) wmma::fill_fragment(acc2[j], 0.f);
            const __nv_bfloat16* As[3] = {ghi, glo, ghi};
            const __nv_bfloat16* Bs[3] = {w2hi, w2hi, w2lo};
#pragma unroll
            for (int p = 0; p < 3; p++) {
#pragma unroll
                for (int ks = 0; ks < 8; ks++) {
                    wmma::fragment<wmma::matrix_a, 16, 16, 16, __nv_bfloat16, wmma::row_major> af;
                    wmma::load_matrix_sync(af, As[p] + rt*16*DIN + ks*16, DIN);
#pragma unroll
                    for (int j = 0; j < 2; j++) {
                        int ct = ct0 + 2*j;
                        wmma::fragment<wmma::matrix_b, 16, 16, 16, __nv_bfloat16, wmma::row_major> bf;
                        wmma::load_matrix_sync(bf, Bs[p] + ks*16*64 + ct*16, 64);
                        wmma::mma_sync(acc2[j], af, bf, acc2[j]);
                    }
                }
            }
#pragma unroll
            for (int j = 0; j < 2; j++)
                wmma::store_matrix_sync(d2 + rt*16*64 + (ct0 + 2*j)*16, acc2[j], 64, wmma::mem_row_major);
        }
        __syncthreads();

        // ---- add fc2 bias ----
        for (int i = t; i < TROWS*DD; i += 256) d2[i] += b2s[i & 63];
        __syncthreads();

        // ---- rms per row ----
        if (t < rvalid) {
            const float* row = d2 + t*DD;
            float s = 0.f;
#pragma unroll
            for (int dd = 0; dd < DD; dd++) { float v = row[(dd + t) & 63]; s += v*v; }
            rr[t] = rsqrtf(s * (1.f/DD) + EPS);
        }
        __syncthreads();

        // ---- y = rmsnorm*rms_w + h_input; BN partials ----
        {
            float* ydst = g_y + (size_t)n0*(LL*DD);
#pragma unroll
            for (int ri = 0; ri < 16; ri++) {
                int r = r0y + ri;
                if (r < rvalid) {
                    float v = d2[r*DD + dch] * rr[r] * rw + hsrc[r*DD + dch];
                    ydst[r*DD + dch] = v;
                    bsum += v; bsq += v*v;
                }
            }
        }
        __syncthreads();   // before next tile overwrites smem
    }

    // ---- BN reduction ----
    bnp[t] = bsum;
    bnp[256 + t] = bsq;
    __syncthreads();
    if (t < DD) {
        float s  = bnp[t] + bnp[t+64] + bnp[t+128] + bnp[t+192];
        float s2 = bnp[256+t] + bnp[256+t+64] + bnp[256+t+128] + bnp[256+t+192];
        atomicAdd(&g_bnsum[t], s);
        atomicAdd(&g_bnsq[t], s2);
    }
}

// ---------------- K5: BN apply + ReLU6 + L-aggregation + residual ----------------
__global__ void k5(const float* __restrict__ hs, const float* __restrict__ gamma,
                   const float* __restrict__ beta, const float* __restrict__ aggw,
                   const float* __restrict__ aggb, float* __restrict__ out) {
    int idx = blockIdx.x*256 + threadIdx.x;
    int d = idx & 63;
    float cnt = (float)(NN*LL);
    float mean = g_bnsum[d] / cnt;
    float var  = g_bnsq[d] / cnt - mean*mean;
    float is = rsqrtf(var + EPS);
    float ga = __ldg(&gamma[d]) * is;
    float be = __ldg(&beta[d]) - mean * ga;
    const float* yrow = g_y + (size_t)(idx >> 6)*(LL*DD);
    float s = __ldg(&aggb[0]);
#pragma unroll
    for (int l = 0; l < LL; l++) {
        float v = yrow[l*DD + d] * ga + be;
        v = fminf(fmaxf(v, 0.f), 6.f);
        s += v * __ldg(&aggw[l]);
    }
    out[idx] = s + hs[idx];
}

// ---------------- host ----------------
extern "C" void kernel_launch(void* const* d_in, const int* in_sizes, int n_in,
                              void* d_out, int out_size) {
    const float* hs     = (const float*)d_in[0];
    const float* hs_e   = (const float*)d_in[1];
    const float* degree = (const float*)d_in[2];
    const float* noise  = (const float*)d_in[3];
    const float* fc1w   = (const float*)d_in[4];
    const float* fc1b   = (const float*)d_in[5];
    const float* convw  = (const float*)d_in[6];
    const float* convb  = (const float*)d_in[7];
    const float* fc2w   = (const float*)d_in[8];
    const float* fc2b   = (const float*)d_in[9];
    const float* rmsw   = (const float*)d_in[10];
    const float* gamma  = (const float*)d_in[11];
    const float* beta   = (const float*)d_in[12];
    const float* aggw   = (const float*)d_in[13];
    const float* aggb   = (const float*)d_in[14];
    const int*   src    = (const int*)d_in[15];
    float* out = (float*)d_out;

    cudaFuncSetAttribute(k3, cudaFuncAttributeMaxDynamicSharedMemorySize, SMEM3);

    kz<<<1, 64>>>();
    k1<<<NN/4, 256>>>(hs, hs_e, degree, noise);
    k2<<<NN, 256>>>(hs, src);
    k3<<<148, 256, SMEM3>>>(fc1w, fc1b, convw, convb, fc2w, fc2b, rmsw);
    k5<<<NN*DD/256, 256>>>(hs, gamma, beta, aggw, aggb, out);
}